// round 12
// baseline (speedup 1.0000x reference)
#include <cuda_runtime.h>
#include <cuda_bf16.h>
#include <cstdint>
#include <math.h>

// ---------------- problem constants ----------------
#define T 1024
#define H 1024
#define II 512        // moe intermediate
#define E 32
#define KTOP 4
#define G 8
#define TG 4
#define CAP 256
#define SCALEF 2.5f
#define IS 1024       // I * NS (shared expert intermediate)

// ---------------- device scratch (static, allocation-free) ----------------
__device__ int   g_topk_idx[T * KTOP];
__device__ float g_tw[T * KTOP];
__device__ int   g_token_slot[T * KTOP];           // slot id (e*CAP+pos) or -1
__device__ int   g_slot_token[E * CAP];
__device__ int   g_expert_count[E];
__device__ float g_gu[(size_t)E * CAP * 2 * II];   // 32 MB raw gate_up outputs
__device__ float g_act[(size_t)E * CAP * II];      // 16 MB
__device__ float g_shared_gu[(size_t)T * 2 * IS];  // 8 MB
__device__ float g_shared_act[(size_t)T * IS];     // 4 MB
__device__ float g_ye[(size_t)E * CAP * H];        // 32 MB

// ---------------- small PTX helpers ----------------
__device__ __forceinline__ uint32_t smem_u32(const void* p) {
    uint32_t a;
    asm("{ .reg .u64 t; cvta.to.shared.u64 t, %1; cvt.u32.u64 %0, t; }" : "=r"(a) : "l"(p));
    return a;
}

#define STS128(r0, r1, r2, r3, addr) \
    asm volatile("st.shared.v4.b32 [%0], {%1, %2, %3, %4};" \
        :: "r"(addr), "r"(r0), "r"(r1), "r"(r2), "r"(r3) : "memory")

#define LDSM_X4(r0, r1, r2, r3, addr) \
    asm volatile("ldmatrix.sync.aligned.m8n8.x4.shared.b16 {%0,%1,%2,%3}, [%4];" \
        : "=r"(r0), "=r"(r1), "=r"(r2), "=r"(r3) : "r"(addr))

#define LDSM_X2(r0, r1, addr) \
    asm volatile("ldmatrix.sync.aligned.m8n8.x2.shared.b16 {%0,%1}, [%2];" \
        : "=r"(r0), "=r"(r1) : "r"(addr))

#define MMA16816(d, a0, a1, a2, a3, b0, b1) \
    asm volatile("mma.sync.aligned.m16n8k16.row.col.f32.bf16.bf16.f32 " \
        "{%0,%1,%2,%3}, {%4,%5,%6,%7}, {%8,%9}, {%0,%1,%2,%3};" \
        : "+f"((d)[0]), "+f"((d)[1]), "+f"((d)[2]), "+f"((d)[3]) \
        : "r"(a0), "r"(a1), "r"(a2), "r"(a3), "r"(b0), "r"(b1))

// ---------------- bf16 split helpers (truncation hi + rn lo) ----------------
__device__ __forceinline__ uint32_t pack_hi(float a, float b) {
    uint32_t ab = __float_as_uint(a) & 0xffff0000u;
    uint32_t bb = __float_as_uint(b) & 0xffff0000u;
    return __byte_perm(ab, bb, 0x7632);
}
__device__ __forceinline__ uint32_t pack_lo(float a, float b) {
    float ar = a - __uint_as_float(__float_as_uint(a) & 0xffff0000u);
    float br = b - __uint_as_float(__float_as_uint(b) & 0xffff0000u);
    __nv_bfloat162 p = __floats2bfloat162_rn(ar, br);
    return *reinterpret_cast<uint32_t*>(&p);
}
// store 16 floats (4x float4) as bf16 hi plane + lo plane (16B + 16B each)
__device__ __forceinline__ void sts_chunk16(uint32_t hi_addr, uint32_t lo_addr,
                                            const float4* f)
{
    uint32_t h0 = pack_hi(f[0].x, f[0].y), h1 = pack_hi(f[0].z, f[0].w);
    uint32_t h2 = pack_hi(f[1].x, f[1].y), h3 = pack_hi(f[1].z, f[1].w);
    STS128(h0, h1, h2, h3, hi_addr);
    uint32_t h4 = pack_hi(f[2].x, f[2].y), h5 = pack_hi(f[2].z, f[2].w);
    uint32_t h6 = pack_hi(f[3].x, f[3].y), h7 = pack_hi(f[3].z, f[3].w);
    STS128(h4, h5, h6, h7, hi_addr + 16);
    uint32_t l0 = pack_lo(f[0].x, f[0].y), l1 = pack_lo(f[0].z, f[0].w);
    uint32_t l2 = pack_lo(f[1].x, f[1].y), l3 = pack_lo(f[1].z, f[1].w);
    STS128(l0, l1, l2, l3, lo_addr);
    uint32_t l4 = pack_lo(f[2].x, f[2].y), l5 = pack_lo(f[2].z, f[2].w);
    uint32_t l6 = pack_lo(f[3].x, f[3].y), l7 = pack_lo(f[3].z, f[3].w);
    STS128(l4, l5, l6, l7, lo_addr + 16);
}

__device__ __forceinline__ void ldg16(float4* pf, const float* src, bool valid)
{
    if (valid) {
        const float4* p = (const float4*)src;
        pf[0] = p[0]; pf[1] = p[1]; pf[2] = p[2]; pf[3] = p[3];
    } else {
        pf[0] = pf[1] = pf[2] = pf[3] = make_float4(0.f, 0.f, 0.f, 0.f);
    }
}

// ---------------- gate + noaux_tc routing (8 tokens / block) ----------------
__global__ __launch_bounds__(256) void gate_kernel(const float* __restrict__ x,
                                                   const float* __restrict__ gate_w,
                                                   const float* __restrict__ e_bias)
{
    __shared__ float xs[8][H / 8 * 8];   // 8 x 1024
    __shared__ float s_sc[8][E];
    __shared__ float s_sfc[8][E];

    int tid = threadIdx.x;
    int wid = tid >> 5;
    int lane = tid & 31;
    int tok0 = blockIdx.x * 8;

    float4* xs4 = (float4*)&xs[0][0];
    const float4* xr = (const float4*)(x + (size_t)tok0 * H);
    for (int i = tid; i < 8 * H / 4; i += 256) xs4[i] = xr[i];
    __syncthreads();

    {
        const float4* w4 = (const float4*)(gate_w + (size_t)lane * H);
        const float4* xv = (const float4*)&xs[wid][0];
        float acc = 0.f;
#pragma unroll 8
        for (int i = 0; i < H / 4; i++) {
            float4 a = xv[i]; float4 b = w4[i];
            acc += a.x * b.x; acc += a.y * b.y; acc += a.z * b.z; acc += a.w * b.w;
        }
        float sc = 1.f / (1.f + expf(-acc));
        s_sc[wid][lane] = sc;
        s_sfc[wid][lane] = sc + e_bias[lane];
    }
    __syncwarp();

    if (lane == 0) {
        int t = tok0 + wid;
        float* sfc = s_sfc[wid];
        float* scores = s_sc[wid];
        float gs[G];
#pragma unroll
        for (int g = 0; g < G; g++) {
            float a0 = sfc[4*g], a1 = sfc[4*g+1], a2 = sfc[4*g+2], a3 = sfc[4*g+3];
            float h1 = fmaxf(a0, a1), l1 = fminf(a0, a1);
            float h2 = fmaxf(a2, a3), l2 = fminf(a2, a3);
            gs[g] = fmaxf(h1, h2) + fmaxf(fminf(h1, h2), fmaxf(l1, l2));
        }
        bool sel[G];
#pragma unroll
        for (int g = 0; g < G; g++) sel[g] = false;
        for (int r = 0; r < TG; r++) {
            int best = -1; float bv = -1e30f;
            for (int g = 0; g < G; g++)
                if (!sel[g] && gs[g] > bv) { bv = gs[g]; best = g; }
            sel[best] = true;
        }
        float m[E];
        for (int e2 = 0; e2 < E; e2++) m[e2] = sel[e2 >> 2] ? sfc[e2] : 0.f;
        int idx[KTOP]; float w[KTOP]; float s = 0.f;
        for (int r = 0; r < KTOP; r++) {
            int best = 0; float bv = -1e30f;
            for (int e2 = 0; e2 < E; e2++)
                if (m[e2] > bv) { bv = m[e2]; best = e2; }
            m[best] = -1e30f;
            idx[r] = best; w[r] = scores[best]; s += w[r];
        }
        s += 1e-20f;
        for (int r = 0; r < KTOP; r++) {
            g_topk_idx[t * KTOP + r] = idx[r];
            g_tw[t * KTOP + r] = w[r] / s * SCALEF;
        }
    }
}

// ---------------- parallel capacity dispatch (segmented scan) ----------------
__global__ __launch_bounds__(1024) void dispatch_kernel()
{
    __shared__ int ef[T * KTOP];        // 16 KB
    __shared__ int posseg[T * KTOP];    // 16 KB
    __shared__ int scnt[32][E];         // 4 KB

    int tid = threadIdx.x;
    int wid = tid >> 5;
    int lane = tid & 31;

    for (int i = tid; i < T * KTOP; i += 1024) ef[i] = g_topk_idx[i];
    ((int*)scnt)[tid] = 0;
    __syncthreads();

    // step 1: per-warp segment of 128 elements, sequential 4 rounds of 32
#pragma unroll
    for (int r = 0; r < 4; r++) {
        int j = wid * 128 + r * 32 + lane;
        int e = ef[j];
        unsigned mask = __match_any_sync(0xffffffffu, e);
        int prior = __popc(mask & ((1u << lane) - 1u));
        int base = scnt[wid][e];
        __syncwarp();
        if (lane == (__ffs(mask) - 1)) scnt[wid][e] = base + __popc(mask);
        __syncwarp();
        posseg[j] = base + prior;
    }
    __syncthreads();

    // step 2: exclusive prefix across the 32 segments, per expert (lane=expert)
    if (wid == 0) {
        int run = 0;
#pragma unroll
        for (int w = 0; w < 32; w++) {
            int c = scnt[w][lane];
            scnt[w][lane] = run;
            run += c;
        }
        g_expert_count[lane] = run < CAP ? run : CAP;
    }
    __syncthreads();

    // step 3: final positions + slot tables
    for (int i = tid; i < T * KTOP; i += 1024) {
        int e = ef[i];
        int pos = scnt[i >> 7][e] + posseg[i];
        if (pos < CAP) {
            g_slot_token[e * CAP + pos] = i >> 2;
            g_token_slot[i] = e * CAP + pos;
        } else {
            g_token_slot[i] = -1;
        }
    }
}

// ---------------- unified bf16-split mma.sync GEMM (double-buffered) ----------------
// C[M,N] = A[M,K] . B[N,K]^T   block 128x128, warp 64x32, K-chunk 32
// PHASE 1: expert gate_up (blocks [0,512)) + shared gate_up (blocks [512,640))
// PHASE 2: expert down    (blocks [0,512)) + shared down    (blocks [512,576))
#define ROWB 80            // smem row pitch bytes (64B data + 16B pad)
#define PLANE (128 * ROWB) // 10240 bytes per plane
#define STAGE (4 * PLANE)  // Ah | Al | Bh | Bl = 40960 bytes

template<int PHASE>
__global__ __launch_bounds__(256, 2) void mma_gemm(
    const float* __restrict__ x,
    const float* __restrict__ wgu,  const float* __restrict__ wdn,
    const float* __restrict__ wgus, const float* __restrict__ wds,
    float* __restrict__ out)
{
    extern __shared__ char dynsmem[];
    __shared__ int s_toks[128];

    const int bid = blockIdx.x;
    const bool expert = bid < 512;

    int e = 0, n0, row0;
    if (expert) {
        e = bid >> 4;
        int rem = bid & 15;
        n0 = (rem & 7) * 128;
        row0 = (rem >> 3) * 128;
        if (row0 >= g_expert_count[e]) return;
    } else {
        int b = bid - 512;
        if (PHASE == 1) { n0 = (b & 15) * 128; row0 = (b >> 4) * 128; }
        else            { n0 = (b & 7)  * 128; row0 = (b >> 3) * 128; }
    }

    const int tid = threadIdx.x;
    const int wid = tid >> 5;
    const int lane = tid & 31;

    if (PHASE == 1 && expert) {
        if (tid < 128) {
            int r = row0 + tid;
            s_toks[tid] = (r < g_expert_count[e]) ? g_slot_token[e * CAP + r] : -1;
        }
        __syncthreads();
    }

    // ---- loader mapping: thread -> row r = tid/2, 16-float half c0 ----
    const int r  = tid >> 1;
    const int c0 = (tid & 1) * 16;

    const float* aptr;
    const float* bptr;
    bool avalid = true;
    int KD;
    if (PHASE == 1) {
        KD = 1024;
        if (expert) {
            int tok = s_toks[r];
            avalid = (tok >= 0);
            aptr = x + (size_t)(avalid ? tok : 0) * H + c0;
            bptr = wgu + ((size_t)e * 2 * II + n0 + r) * H + c0;
        } else {
            aptr = x + (size_t)(row0 + r) * H + c0;
            bptr = wgus + (size_t)(n0 + r) * H + c0;
        }
    } else {
        if (expert) {
            KD = II;
            aptr = g_act + ((size_t)e * CAP + row0 + r) * II + c0;
            bptr = wdn + ((size_t)e * H + n0 + r) * II + c0;
        } else {
            KD = 1024;
            aptr = g_shared_act + (size_t)(row0 + r) * IS + c0;
            bptr = wds + (size_t)(n0 + r) * IS + c0;
        }
    }
    const int NCH = KD / 32;

    const uint32_t sdyn = smem_u32(dynsmem);
    const uint32_t sa_off = (uint32_t)(r * ROWB + c0 * 2);            // within Ah plane
    const uint32_t sb_off = (uint32_t)(2 * PLANE + r * ROWB + c0 * 2);// within stage (Bh)

    // ---- compute mapping ----
    const int warp_m = wid >> 2;
    const int warp_n = wid & 3;
    const uint32_t a_off = (uint32_t)((warp_m * 64 + (lane & 15)) * ROWB + ((lane >> 4) << 4));
    const uint32_t b_off = (uint32_t)(2 * PLANE + (warp_n * 32 + (lane & 7)) * ROWB + (((lane >> 3) & 1) << 4));

    float acc[4][4][4];
#pragma unroll
    for (int mt = 0; mt < 4; mt++)
#pragma unroll
        for (int nt = 0; nt < 4; nt++)
#pragma unroll
            for (int q = 0; q < 4; q++) acc[mt][nt][q] = 0.f;

#define COMPUTE_S(base, s) do { \
    uint32_t bh[4][2], bl[4][2]; \
    _Pragma("unroll") \
    for (int nt = 0; nt < 4; nt++) { \
        uint32_t addr = (base) + b_off + (uint32_t)(nt * 8 * ROWB + (s) * 32); \
        LDSM_X2(bh[nt][0], bh[nt][1], addr); \
        LDSM_X2(bl[nt][0], bl[nt][1], addr + PLANE); \
    } \
    _Pragma("unroll") \
    for (int mt = 0; mt < 4; mt++) { \
        uint32_t addr = (base) + a_off + (uint32_t)(mt * 16 * ROWB + (s) * 32); \
        uint32_t ah0, ah1, ah2, ah3, al0, al1, al2, al3; \
        LDSM_X4(ah0, ah1, ah2, ah3, addr); \
        LDSM_X4(al0, al1, al2, al3, addr + PLANE); \
        _Pragma("unroll") \
        for (int nt = 0; nt < 4; nt++) { \
            MMA16816(acc[mt][nt], ah0, ah1, ah2, ah3, bh[nt][0], bh[nt][1]); \
            MMA16816(acc[mt][nt], ah0, ah1, ah2, ah3, bl[nt][0], bl[nt][1]); \
            MMA16816(acc[mt][nt], al0, al1, al2, al3, bh[nt][0], bh[nt][1]); \
        } \
    } \
} while (0)

    // ---- prologue: stage chunk 0 into buffer 0 ----
    {
        float4 pf[4];
        ldg16(pf, aptr, avalid);
        sts_chunk16(sdyn + sa_off, sdyn + PLANE + sa_off, pf);
        ldg16(pf, bptr, true);
        sts_chunk16(sdyn + sb_off, sdyn + PLANE + sb_off, pf);
    }
    __syncthreads();

    // ---- main loop: one barrier per chunk, loads overlapped with MMA ----
    for (int kc = 0; kc < NCH; kc++) {
        const uint32_t cur = sdyn + (uint32_t)(kc & 1) * STAGE;
        const uint32_t nxt = sdyn + (uint32_t)((kc + 1) & 1) * STAGE;
        const bool hn = (kc + 1 < NCH);

        float4 pf[4];
        if (hn) ldg16(pf, aptr + (kc + 1) * 32, avalid);
        COMPUTE_S(cur, 0);
        if (hn) {
            sts_chunk16(nxt + sa_off, nxt + PLANE + sa_off, pf);
            ldg16(pf, bptr + (kc + 1) * 32, true);
        }
        COMPUTE_S(cur, 1);
        if (hn) sts_chunk16(nxt + sb_off, nxt + PLANE + sb_off, pf);
        __syncthreads();
    }
#undef COMPUTE_S

    // ---- epilogue: plain fp32 stores ----
    float* Cb;
    int CSTR;
    if (PHASE == 1) {
        if (expert) { Cb = g_gu + (size_t)e * CAP * 2 * II; CSTR = 2 * II; }
        else        { Cb = g_shared_gu;                     CSTR = 2 * IS; }
    } else {
        if (expert) { Cb = g_ye + (size_t)e * CAP * H;      CSTR = H; }
        else        { Cb = out;                             CSTR = H; }
    }

#pragma unroll
    for (int mt = 0; mt < 4; mt++) {
        int row = row0 + warp_m * 64 + mt * 16 + (lane >> 2);
#pragma unroll
        for (int nt = 0; nt < 4; nt++) {
            int col = n0 + warp_n * 32 + nt * 8 + (lane & 3) * 2;
            *(float2*)(Cb + (size_t)row * CSTR + col) =
                make_float2(acc[mt][nt][0], acc[mt][nt][1]);
            *(float2*)(Cb + (size_t)(row + 8) * CSTR + col) =
                make_float2(acc[mt][nt][2], acc[mt][nt][3]);
        }
    }
}

// ---------------- merged silu-and-mul ----------------
__device__ __forceinline__ float4 silu_mul4(float4 g, float4 u) {
    float4 r;
    r.x = g.x / (1.f + expf(-g.x)) * u.x;
    r.y = g.y / (1.f + expf(-g.y)) * u.y;
    r.z = g.z / (1.f + expf(-g.z)) * u.z;
    r.w = g.w / (1.f + expf(-g.w)) * u.w;
    return r;
}

#define SHN (T * IS / 4)            // 262144 float4 units (shared)
#define EXN (E * CAP * II / 4)      // 1048576 float4 units (expert)

__global__ void silu_kernel()
{
    int idx = blockIdx.x * 256 + threadIdx.x;
    if (idx < SHN) {
        int r = idx / (IS / 4), i = idx % (IS / 4);
        float4 g = *(const float4*)&g_shared_gu[(size_t)r * 2 * IS + i * 4];
        float4 u = *(const float4*)&g_shared_gu[(size_t)r * 2 * IS + IS + i * 4];
        *(float4*)&g_shared_act[(size_t)r * IS + i * 4] = silu_mul4(g, u);
    } else {
        int j = idx - SHN;
        int r = j / (II / 4), i = j % (II / 4);
        float4 g = *(const float4*)&g_gu[(size_t)r * 2 * II + i * 4];
        float4 u = *(const float4*)&g_gu[(size_t)r * 2 * II + II + i * 4];
        *(float4*)&g_act[(size_t)r * II + i * 4] = silu_mul4(g, u);
    }
}

// ---------------- final combine: out += sum_k w_k * ye[slot] ----------------
__global__ void combine_kernel(float* __restrict__ out)
{
    int t = blockIdx.x;
    int h4 = threadIdx.x;
    float4* orow = (float4*)(out + (size_t)t * H);
    float4 acc = orow[h4];
#pragma unroll
    for (int k = 0; k < KTOP; k++) {
        int slot = g_token_slot[t * KTOP + k];
        if (slot >= 0) {
            float w = g_tw[t * KTOP + k];
            float4 y = ((const float4*)(g_ye + (size_t)slot * H))[h4];
            acc.x += w * y.x; acc.y += w * y.y; acc.z += w * y.z; acc.w += w * y.w;
        }
    }
    orow[h4] = acc;
}

// ---------------- launcher ----------------
extern "C" void kernel_launch(void* const* d_in, const int* in_sizes, int n_in,
                              void* d_out, int out_size)
{
    (void)in_sizes; (void)n_in; (void)out_size;
    const float* x    = (const float*)d_in[0];   // (T,H)
    const float* gw   = (const float*)d_in[1];   // (E,H)
    const float* eb   = (const float*)d_in[2];   // (E,)
    const float* wgu  = (const float*)d_in[3];   // (E,2I,H)
    const float* wdn  = (const float*)d_in[4];   // (E,H,I)
    const float* wgus = (const float*)d_in[5];   // (2*IS,H)
    const float* wds  = (const float*)d_in[6];   // (H,IS)
    float* out = (float*)d_out;                  // (T,H)

    constexpr int DSMEM = 2 * STAGE;  // 81920
    static bool attr_done = false;
    if (!attr_done) {
        cudaFuncSetAttribute((const void*)mma_gemm<1>,
                             cudaFuncAttributeMaxDynamicSharedMemorySize, DSMEM);
        cudaFuncSetAttribute((const void*)mma_gemm<2>,
                             cudaFuncAttributeMaxDynamicSharedMemorySize, DSMEM);
        attr_done = true;
    }

    gate_kernel<<<T / 8, 256>>>(x, gw, eb);
    dispatch_kernel<<<1, 1024>>>();

    // gate_up GEMMs: expert (512 blocks) + shared (128 blocks)
    mma_gemm<1><<<640, 256, DSMEM>>>(x, wgu, wdn, wgus, wds, out);
    silu_kernel<<<(SHN + EXN) / 256, 256>>>();
    // down GEMMs: expert (512 blocks) + shared (64 blocks)
    mma_gemm<2><<<576, 256, DSMEM>>>(x, wgu, wdn, wgus, wds, out);

    combine_kernel<<<T, 256>>>(out);
}

// round 13
// speedup vs baseline: 1.0015x; 1.0015x over previous
#include <cuda_runtime.h>
#include <cuda_bf16.h>
#include <cstdint>
#include <math.h>

// ---------------- problem constants ----------------
#define T 1024
#define H 1024
#define II 512        // moe intermediate
#define E 32
#define KTOP 4
#define G 8
#define TG 4
#define CAP 256
#define SCALEF 2.5f
#define IS 1024       // I * NS (shared expert intermediate)

// ---------------- device scratch (static, allocation-free) ----------------
__device__ int   g_topk_idx[T * KTOP];
__device__ float g_tw[T * KTOP];
__device__ int   g_token_slot[T * KTOP];           // slot id (e*CAP+pos) or -1
__device__ int   g_slot_token[E * CAP];
__device__ int   g_expert_count[E];
__device__ float g_gu[(size_t)E * CAP * 2 * II];   // 32 MB raw gate_up outputs
__device__ float g_act[(size_t)E * CAP * II];      // 16 MB
__device__ float g_shared_gu[(size_t)T * 2 * IS];  // 8 MB
__device__ float g_shared_act[(size_t)T * IS];     // 4 MB
__device__ float g_ye[(size_t)E * CAP * H];        // 32 MB

// ---------------- small PTX helpers ----------------
__device__ __forceinline__ uint32_t smem_u32(const void* p) {
    uint32_t a;
    asm("{ .reg .u64 t; cvta.to.shared.u64 t, %1; cvt.u32.u64 %0, t; }" : "=r"(a) : "l"(p));
    return a;
}

#define STS128(r0, r1, r2, r3, addr) \
    asm volatile("st.shared.v4.b32 [%0], {%1, %2, %3, %4};" \
        :: "r"(addr), "r"(r0), "r"(r1), "r"(r2), "r"(r3) : "memory")

#define LDSM_X4(r0, r1, r2, r3, addr) \
    asm volatile("ldmatrix.sync.aligned.m8n8.x4.shared.b16 {%0,%1,%2,%3}, [%4];" \
        : "=r"(r0), "=r"(r1), "=r"(r2), "=r"(r3) : "r"(addr))

#define LDSM_X2(r0, r1, addr) \
    asm volatile("ldmatrix.sync.aligned.m8n8.x2.shared.b16 {%0,%1}, [%2];" \
        : "=r"(r0), "=r"(r1) : "r"(addr))

#define MMA16816(d, a0, a1, a2, a3, b0, b1) \
    asm volatile("mma.sync.aligned.m16n8k16.row.col.f32.bf16.bf16.f32 " \
        "{%0,%1,%2,%3}, {%4,%5,%6,%7}, {%8,%9}, {%0,%1,%2,%3};" \
        : "+f"((d)[0]), "+f"((d)[1]), "+f"((d)[2]), "+f"((d)[3]) \
        : "r"(a0), "r"(a1), "r"(a2), "r"(a3), "r"(b0), "r"(b1))

// ---------------- bf16 split helpers (truncation hi + rn lo) ----------------
__device__ __forceinline__ uint32_t pack_hi(float a, float b) {
    uint32_t ab = __float_as_uint(a) & 0xffff0000u;
    uint32_t bb = __float_as_uint(b) & 0xffff0000u;
    return __byte_perm(ab, bb, 0x7632);
}
__device__ __forceinline__ uint32_t pack_lo(float a, float b) {
    float ar = a - __uint_as_float(__float_as_uint(a) & 0xffff0000u);
    float br = b - __uint_as_float(__float_as_uint(b) & 0xffff0000u);
    __nv_bfloat162 p = __floats2bfloat162_rn(ar, br);
    return *reinterpret_cast<uint32_t*>(&p);
}
// store 16 floats (4x float4) as bf16 hi plane + lo plane (16B + 16B each)
__device__ __forceinline__ void sts_chunk16(uint32_t hi_addr, uint32_t lo_addr,
                                            const float4* f)
{
    uint32_t h0 = pack_hi(f[0].x, f[0].y), h1 = pack_hi(f[0].z, f[0].w);
    uint32_t h2 = pack_hi(f[1].x, f[1].y), h3 = pack_hi(f[1].z, f[1].w);
    STS128(h0, h1, h2, h3, hi_addr);
    uint32_t h4 = pack_hi(f[2].x, f[2].y), h5 = pack_hi(f[2].z, f[2].w);
    uint32_t h6 = pack_hi(f[3].x, f[3].y), h7 = pack_hi(f[3].z, f[3].w);
    STS128(h4, h5, h6, h7, hi_addr + 16);
    uint32_t l0 = pack_lo(f[0].x, f[0].y), l1 = pack_lo(f[0].z, f[0].w);
    uint32_t l2 = pack_lo(f[1].x, f[1].y), l3 = pack_lo(f[1].z, f[1].w);
    STS128(l0, l1, l2, l3, lo_addr);
    uint32_t l4 = pack_lo(f[2].x, f[2].y), l5 = pack_lo(f[2].z, f[2].w);
    uint32_t l6 = pack_lo(f[3].x, f[3].y), l7 = pack_lo(f[3].z, f[3].w);
    STS128(l4, l5, l6, l7, lo_addr + 16);
}

__device__ __forceinline__ void ldg16(float4* pf, const float* src, bool valid)
{
    if (valid) {
        const float4* p = (const float4*)src;
        pf[0] = p[0]; pf[1] = p[1]; pf[2] = p[2]; pf[3] = p[3];
    } else {
        pf[0] = pf[1] = pf[2] = pf[3] = make_float4(0.f, 0.f, 0.f, 0.f);
    }
}

// ---------------- gate + noaux_tc routing (8 tokens / block) ----------------
__global__ __launch_bounds__(256) void gate_kernel(const float* __restrict__ x,
                                                   const float* __restrict__ gate_w,
                                                   const float* __restrict__ e_bias)
{
    __shared__ float xs[8][H / 8 * 8];   // 8 x 1024
    __shared__ float s_sc[8][E];
    __shared__ float s_sfc[8][E];

    int tid = threadIdx.x;
    int wid = tid >> 5;
    int lane = tid & 31;
    int tok0 = blockIdx.x * 8;

    float4* xs4 = (float4*)&xs[0][0];
    const float4* xr = (const float4*)(x + (size_t)tok0 * H);
    for (int i = tid; i < 8 * H / 4; i += 256) xs4[i] = xr[i];
    __syncthreads();

    {
        const float4* w4 = (const float4*)(gate_w + (size_t)lane * H);
        const float4* xv = (const float4*)&xs[wid][0];
        float acc = 0.f;
#pragma unroll 8
        for (int i = 0; i < H / 4; i++) {
            float4 a = xv[i]; float4 b = w4[i];
            acc += a.x * b.x; acc += a.y * b.y; acc += a.z * b.z; acc += a.w * b.w;
        }
        float sc = 1.f / (1.f + expf(-acc));
        s_sc[wid][lane] = sc;
        s_sfc[wid][lane] = sc + e_bias[lane];
    }
    __syncwarp();

    if (lane == 0) {
        int t = tok0 + wid;
        float* sfc = s_sfc[wid];
        float* scores = s_sc[wid];
        float gs[G];
#pragma unroll
        for (int g = 0; g < G; g++) {
            float a0 = sfc[4*g], a1 = sfc[4*g+1], a2 = sfc[4*g+2], a3 = sfc[4*g+3];
            float h1 = fmaxf(a0, a1), l1 = fminf(a0, a1);
            float h2 = fmaxf(a2, a3), l2 = fminf(a2, a3);
            gs[g] = fmaxf(h1, h2) + fmaxf(fminf(h1, h2), fmaxf(l1, l2));
        }
        bool sel[G];
#pragma unroll
        for (int g = 0; g < G; g++) sel[g] = false;
        for (int r = 0; r < TG; r++) {
            int best = -1; float bv = -1e30f;
            for (int g = 0; g < G; g++)
                if (!sel[g] && gs[g] > bv) { bv = gs[g]; best = g; }
            sel[best] = true;
        }
        float m[E];
        for (int e2 = 0; e2 < E; e2++) m[e2] = sel[e2 >> 2] ? sfc[e2] : 0.f;
        int idx[KTOP]; float w[KTOP]; float s = 0.f;
        for (int r = 0; r < KTOP; r++) {
            int best = 0; float bv = -1e30f;
            for (int e2 = 0; e2 < E; e2++)
                if (m[e2] > bv) { bv = m[e2]; best = e2; }
            m[best] = -1e30f;
            idx[r] = best; w[r] = scores[best]; s += w[r];
        }
        s += 1e-20f;
        for (int r = 0; r < KTOP; r++) {
            g_topk_idx[t * KTOP + r] = idx[r];
            g_tw[t * KTOP + r] = w[r] / s * SCALEF;
        }
    }
}

// ---------------- parallel capacity dispatch (segmented scan) ----------------
__global__ __launch_bounds__(1024) void dispatch_kernel()
{
    __shared__ int ef[T * KTOP];        // 16 KB
    __shared__ int posseg[T * KTOP];    // 16 KB
    __shared__ int scnt[32][E];         // 4 KB

    int tid = threadIdx.x;
    int wid = tid >> 5;
    int lane = tid & 31;

    for (int i = tid; i < T * KTOP; i += 1024) ef[i] = g_topk_idx[i];
    ((int*)scnt)[tid] = 0;
    __syncthreads();

    // step 1: per-warp segment of 128 elements, sequential 4 rounds of 32
#pragma unroll
    for (int r = 0; r < 4; r++) {
        int j = wid * 128 + r * 32 + lane;
        int e = ef[j];
        unsigned mask = __match_any_sync(0xffffffffu, e);
        int prior = __popc(mask & ((1u << lane) - 1u));
        int base = scnt[wid][e];
        __syncwarp();
        if (lane == (__ffs(mask) - 1)) scnt[wid][e] = base + __popc(mask);
        __syncwarp();
        posseg[j] = base + prior;
    }
    __syncthreads();

    // step 2: exclusive prefix across the 32 segments, per expert (lane=expert)
    if (wid == 0) {
        int run = 0;
#pragma unroll
        for (int w = 0; w < 32; w++) {
            int c = scnt[w][lane];
            scnt[w][lane] = run;
            run += c;
        }
        g_expert_count[lane] = run < CAP ? run : CAP;
    }
    __syncthreads();

    // step 3: final positions + slot tables
    for (int i = tid; i < T * KTOP; i += 1024) {
        int e = ef[i];
        int pos = scnt[i >> 7][e] + posseg[i];
        if (pos < CAP) {
            g_slot_token[e * CAP + pos] = i >> 2;
            g_token_slot[i] = e * CAP + pos;
        } else {
            g_token_slot[i] = -1;
        }
    }
}

// ---------------- unified bf16-split mma.sync GEMM (double-buffered) ----------------
// C[M,N] = A[M,K] . B[N,K]^T   block 128x128, warp 64x32, K-chunk 32
// PHASE 1: expert gate_up (blocks [0,512)) + shared gate_up (blocks [512,640))
// PHASE 2: expert down    (blocks [0,512)) + shared down    (blocks [512,576))
#define ROWB 80            // smem row pitch bytes (64B data + 16B pad)
#define PLANE (128 * ROWB) // 10240 bytes per plane
#define STAGE (4 * PLANE)  // Ah | Al | Bh | Bl = 40960 bytes

template<int PHASE>
__global__ __launch_bounds__(256, 2) void mma_gemm(
    const float* __restrict__ x,
    const float* __restrict__ wgu,  const float* __restrict__ wdn,
    const float* __restrict__ wgus, const float* __restrict__ wds,
    float* __restrict__ out)
{
    extern __shared__ char dynsmem[];
    __shared__ int s_toks[128];

    const int bid = blockIdx.x;
    const bool expert = bid < 512;

    int e = 0, n0, row0;
    if (expert) {
        e = bid >> 4;
        int rem = bid & 15;
        n0 = (rem & 7) * 128;
        row0 = (rem >> 3) * 128;
        if (row0 >= g_expert_count[e]) return;
    } else {
        int b = bid - 512;
        if (PHASE == 1) { n0 = (b & 15) * 128; row0 = (b >> 4) * 128; }
        else            { n0 = (b & 7)  * 128; row0 = (b >> 3) * 128; }
    }

    const int tid = threadIdx.x;
    const int wid = tid >> 5;
    const int lane = tid & 31;

    if (PHASE == 1 && expert) {
        if (tid < 128) {
            int r = row0 + tid;
            s_toks[tid] = (r < g_expert_count[e]) ? g_slot_token[e * CAP + r] : -1;
        }
        __syncthreads();
    }

    // ---- loader mapping: thread -> row r = tid/2, 16-float half c0 ----
    const int r  = tid >> 1;
    const int c0 = (tid & 1) * 16;

    const float* aptr;
    const float* bptr;
    bool avalid = true;
    int KD;
    if (PHASE == 1) {
        KD = 1024;
        if (expert) {
            int tok = s_toks[r];
            avalid = (tok >= 0);
            aptr = x + (size_t)(avalid ? tok : 0) * H + c0;
            bptr = wgu + ((size_t)e * 2 * II + n0 + r) * H + c0;
        } else {
            aptr = x + (size_t)(row0 + r) * H + c0;
            bptr = wgus + (size_t)(n0 + r) * H + c0;
        }
    } else {
        if (expert) {
            KD = II;
            aptr = g_act + ((size_t)e * CAP + row0 + r) * II + c0;
            bptr = wdn + ((size_t)e * H + n0 + r) * II + c0;
        } else {
            KD = 1024;
            aptr = g_shared_act + (size_t)(row0 + r) * IS + c0;
            bptr = wds + (size_t)(n0 + r) * IS + c0;
        }
    }
    const int NCH = KD / 32;

    const uint32_t sdyn = smem_u32(dynsmem);
    const uint32_t sa_off = (uint32_t)(r * ROWB + c0 * 2);            // within Ah plane
    const uint32_t sb_off = (uint32_t)(2 * PLANE + r * ROWB + c0 * 2);// within stage (Bh)

    // ---- compute mapping ----
    const int warp_m = wid >> 2;
    const int warp_n = wid & 3;
    const uint32_t a_off = (uint32_t)((warp_m * 64 + (lane & 15)) * ROWB + ((lane >> 4) << 4));
    const uint32_t b_off = (uint32_t)(2 * PLANE + (warp_n * 32 + (lane & 7)) * ROWB + (((lane >> 3) & 1) << 4));

    float acc[4][4][4];
#pragma unroll
    for (int mt = 0; mt < 4; mt++)
#pragma unroll
        for (int nt = 0; nt < 4; nt++)
#pragma unroll
            for (int q = 0; q < 4; q++) acc[mt][nt][q] = 0.f;

#define COMPUTE_S(base, s) do { \
    uint32_t bh[4][2], bl[4][2]; \
    _Pragma("unroll") \
    for (int nt = 0; nt < 4; nt++) { \
        uint32_t addr = (base) + b_off + (uint32_t)(nt * 8 * ROWB + (s) * 32); \
        LDSM_X2(bh[nt][0], bh[nt][1], addr); \
        LDSM_X2(bl[nt][0], bl[nt][1], addr + PLANE); \
    } \
    _Pragma("unroll") \
    for (int mt = 0; mt < 4; mt++) { \
        uint32_t addr = (base) + a_off + (uint32_t)(mt * 16 * ROWB + (s) * 32); \
        uint32_t ah0, ah1, ah2, ah3, al0, al1, al2, al3; \
        LDSM_X4(ah0, ah1, ah2, ah3, addr); \
        LDSM_X4(al0, al1, al2, al3, addr + PLANE); \
        _Pragma("unroll") \
        for (int nt = 0; nt < 4; nt++) { \
            MMA16816(acc[mt][nt], ah0, ah1, ah2, ah3, bh[nt][0], bh[nt][1]); \
            MMA16816(acc[mt][nt], ah0, ah1, ah2, ah3, bl[nt][0], bl[nt][1]); \
            MMA16816(acc[mt][nt], al0, al1, al2, al3, bh[nt][0], bh[nt][1]); \
        } \
    } \
} while (0)

    // ---- prologue: stage chunk 0 into buffer 0 ----
    {
        float4 pf[4];
        ldg16(pf, aptr, avalid);
        sts_chunk16(sdyn + sa_off, sdyn + PLANE + sa_off, pf);
        ldg16(pf, bptr, true);
        sts_chunk16(sdyn + sb_off, sdyn + PLANE + sb_off, pf);
    }
    __syncthreads();

    // ---- main loop: one barrier per chunk, loads overlapped with MMA ----
    for (int kc = 0; kc < NCH; kc++) {
        const uint32_t cur = sdyn + (uint32_t)(kc & 1) * STAGE;
        const uint32_t nxt = sdyn + (uint32_t)((kc + 1) & 1) * STAGE;
        const bool hn = (kc + 1 < NCH);

        float4 pf[4];
        if (hn) ldg16(pf, aptr + (kc + 1) * 32, avalid);
        COMPUTE_S(cur, 0);
        if (hn) {
            sts_chunk16(nxt + sa_off, nxt + PLANE + sa_off, pf);
            ldg16(pf, bptr + (kc + 1) * 32, true);
        }
        COMPUTE_S(cur, 1);
        if (hn) sts_chunk16(nxt + sb_off, nxt + PLANE + sb_off, pf);
        __syncthreads();
    }
#undef COMPUTE_S

    // ---- epilogue: plain fp32 stores ----
    float* Cb;
    int CSTR;
    if (PHASE == 1) {
        if (expert) { Cb = g_gu + (size_t)e * CAP * 2 * II; CSTR = 2 * II; }
        else        { Cb = g_shared_gu;                     CSTR = 2 * IS; }
    } else {
        if (expert) { Cb = g_ye + (size_t)e * CAP * H;      CSTR = H; }
        else        { Cb = out;                             CSTR = H; }
    }

#pragma unroll
    for (int mt = 0; mt < 4; mt++) {
        int row = row0 + warp_m * 64 + mt * 16 + (lane >> 2);
#pragma unroll
        for (int nt = 0; nt < 4; nt++) {
            int col = n0 + warp_n * 32 + nt * 8 + (lane & 3) * 2;
            *(float2*)(Cb + (size_t)row * CSTR + col) =
                make_float2(acc[mt][nt][0], acc[mt][nt][1]);
            *(float2*)(Cb + (size_t)(row + 8) * CSTR + col) =
                make_float2(acc[mt][nt][2], acc[mt][nt][3]);
        }
    }
}

// ---------------- merged silu-and-mul ----------------
__device__ __forceinline__ float4 silu_mul4(float4 g, float4 u) {
    float4 r;
    r.x = g.x / (1.f + expf(-g.x)) * u.x;
    r.y = g.y / (1.f + expf(-g.y)) * u.y;
    r.z = g.z / (1.f + expf(-g.z)) * u.z;
    r.w = g.w / (1.f + expf(-g.w)) * u.w;
    return r;
}

#define SHN (T * IS / 4)            // 262144 float4 units (shared)
#define EXN (E * CAP * II / 4)      // 1048576 float4 units (expert)

__global__ void silu_kernel()
{
    int idx = blockIdx.x * 256 + threadIdx.x;
    if (idx < SHN) {
        int r = idx / (IS / 4), i = idx % (IS / 4);
        float4 g = *(const float4*)&g_shared_gu[(size_t)r * 2 * IS + i * 4];
        float4 u = *(const float4*)&g_shared_gu[(size_t)r * 2 * IS + IS + i * 4];
        *(float4*)&g_shared_act[(size_t)r * IS + i * 4] = silu_mul4(g, u);
    } else {
        int j = idx - SHN;
        int r = j / (II / 4), i = j % (II / 4);
        float4 g = *(const float4*)&g_gu[(size_t)r * 2 * II + i * 4];
        float4 u = *(const float4*)&g_gu[(size_t)r * 2 * II + II + i * 4];
        *(float4*)&g_act[(size_t)r * II + i * 4] = silu_mul4(g, u);
    }
}

// ---------------- final combine: out += sum_k w_k * ye[slot] ----------------
__global__ void combine_kernel(float* __restrict__ out)
{
    int t = blockIdx.x;
    int h4 = threadIdx.x;
    float4* orow = (float4*)(out + (size_t)t * H);
    float4 acc = orow[h4];
#pragma unroll
    for (int k = 0; k < KTOP; k++) {
        int slot = g_token_slot[t * KTOP + k];
        if (slot >= 0) {
            float w = g_tw[t * KTOP + k];
            float4 y = ((const float4*)(g_ye + (size_t)slot * H))[h4];
            acc.x += w * y.x; acc.y += w * y.y; acc.z += w * y.z; acc.w += w * y.w;
        }
    }
    orow[h4] = acc;
}

// ---------------- launcher ----------------
extern "C" void kernel_launch(void* const* d_in, const int* in_sizes, int n_in,
                              void* d_out, int out_size)
{
    (void)in_sizes; (void)n_in; (void)out_size;
    const float* x    = (const float*)d_in[0];   // (T,H)
    const float* gw   = (const float*)d_in[1];   // (E,H)
    const float* eb   = (const float*)d_in[2];   // (E,)
    const float* wgu  = (const float*)d_in[3];   // (E,2I,H)
    const float* wdn  = (const float*)d_in[4];   // (E,H,I)
    const float* wgus = (const float*)d_in[5];   // (2*IS,H)
    const float* wds  = (const float*)d_in[6];   // (H,IS)
    float* out = (float*)d_out;                  // (T,H)

    constexpr int DSMEM = 2 * STAGE;  // 81920
    static bool attr_done = false;
    if (!attr_done) {
        cudaFuncSetAttribute((const void*)mma_gemm<1>,
                             cudaFuncAttributeMaxDynamicSharedMemorySize, DSMEM);
        cudaFuncSetAttribute((const void*)mma_gemm<2>,
                             cudaFuncAttributeMaxDynamicSharedMemorySize, DSMEM);
        attr_done = true;
    }

    gate_kernel<<<T / 8, 256>>>(x, gw, eb);
    dispatch_kernel<<<1, 1024>>>();

    // gate_up GEMMs: expert (512 blocks) + shared (128 blocks)
    mma_gemm<1><<<640, 256, DSMEM>>>(x, wgu, wdn, wgus, wds, out);
    silu_kernel<<<(SHN + EXN) / 256, 256>>>();
    // down GEMMs: expert (512 blocks) + shared (64 blocks)
    mma_gemm<2><<<576, 256, DSMEM>>>(x, wgu, wdn, wgus, wds, out);

    combine_kernel<<<T, 256>>>(out);
}

// round 14
// speedup vs baseline: 1.0053x; 1.0038x over previous
#include <cuda_runtime.h>
#include <cuda_bf16.h>
#include <cstdint>
#include <math.h>

// ---------------- problem constants ----------------
#define T 1024
#define H 1024
#define II 512        // moe intermediate
#define E 32
#define KTOP 4
#define G 8
#define TG 4
#define CAP 256
#define SCALEF 2.5f
#define IS 1024       // I * NS (shared expert intermediate)

// ---------------- device scratch (static, allocation-free) ----------------
__device__ int   g_topk_idx[T * KTOP];
__device__ float g_tw[T * KTOP];
__device__ int   g_token_slot[T * KTOP];           // slot id (e*CAP+pos) or -1
__device__ int   g_slot_token[E * CAP];
__device__ int   g_expert_count[E];
__device__ float g_gu[(size_t)E * CAP * 2 * II];   // 32 MB raw gate_up outputs
__device__ float g_act[(size_t)E * CAP * II];      // 16 MB
__device__ float g_shared_gu[(size_t)T * 2 * IS];  // 8 MB
__device__ float g_shared_act[(size_t)T * IS];     // 4 MB
__device__ float g_ye[(size_t)E * CAP * H];        // 32 MB

// ---------------- small PTX helpers ----------------
__device__ __forceinline__ uint32_t smem_u32(const void* p) {
    uint32_t a;
    asm("{ .reg .u64 t; cvta.to.shared.u64 t, %1; cvt.u32.u64 %0, t; }" : "=r"(a) : "l"(p));
    return a;
}

#define STS128(r0, r1, r2, r3, addr) \
    asm volatile("st.shared.v4.b32 [%0], {%1, %2, %3, %4};" \
        :: "r"(addr), "r"(r0), "r"(r1), "r"(r2), "r"(r3) : "memory")

#define LDSM_X4(r0, r1, r2, r3, addr) \
    asm volatile("ldmatrix.sync.aligned.m8n8.x4.shared.b16 {%0,%1,%2,%3}, [%4];" \
        : "=r"(r0), "=r"(r1), "=r"(r2), "=r"(r3) : "r"(addr))

#define LDSM_X2(r0, r1, addr) \
    asm volatile("ldmatrix.sync.aligned.m8n8.x2.shared.b16 {%0,%1}, [%2];" \
        : "=r"(r0), "=r"(r1) : "r"(addr))

#define MMA16816(d, a0, a1, a2, a3, b0, b1) \
    asm volatile("mma.sync.aligned.m16n8k16.row.col.f32.bf16.bf16.f32 " \
        "{%0,%1,%2,%3}, {%4,%5,%6,%7}, {%8,%9}, {%0,%1,%2,%3};" \
        : "+f"((d)[0]), "+f"((d)[1]), "+f"((d)[2]), "+f"((d)[3]) \
        : "r"(a0), "r"(a1), "r"(a2), "r"(a3), "r"(b0), "r"(b1))

// ---------------- bf16 split helpers (truncation hi + rn lo) ----------------
__device__ __forceinline__ uint32_t pack_hi(float a, float b) {
    uint32_t ab = __float_as_uint(a) & 0xffff0000u;
    uint32_t bb = __float_as_uint(b) & 0xffff0000u;
    return __byte_perm(ab, bb, 0x7632);
}
__device__ __forceinline__ uint32_t pack_lo(float a, float b) {
    float ar = a - __uint_as_float(__float_as_uint(a) & 0xffff0000u);
    float br = b - __uint_as_float(__float_as_uint(b) & 0xffff0000u);
    __nv_bfloat162 p = __floats2bfloat162_rn(ar, br);
    return *reinterpret_cast<uint32_t*>(&p);
}
// store 16 floats (4x float4) as bf16 hi plane + lo plane (16B + 16B each)
__device__ __forceinline__ void sts_chunk16(uint32_t hi_addr, uint32_t lo_addr,
                                            const float4* f)
{
    uint32_t h0 = pack_hi(f[0].x, f[0].y), h1 = pack_hi(f[0].z, f[0].w);
    uint32_t h2 = pack_hi(f[1].x, f[1].y), h3 = pack_hi(f[1].z, f[1].w);
    STS128(h0, h1, h2, h3, hi_addr);
    uint32_t h4 = pack_hi(f[2].x, f[2].y), h5 = pack_hi(f[2].z, f[2].w);
    uint32_t h6 = pack_hi(f[3].x, f[3].y), h7 = pack_hi(f[3].z, f[3].w);
    STS128(h4, h5, h6, h7, hi_addr + 16);
    uint32_t l0 = pack_lo(f[0].x, f[0].y), l1 = pack_lo(f[0].z, f[0].w);
    uint32_t l2 = pack_lo(f[1].x, f[1].y), l3 = pack_lo(f[1].z, f[1].w);
    STS128(l0, l1, l2, l3, lo_addr);
    uint32_t l4 = pack_lo(f[2].x, f[2].y), l5 = pack_lo(f[2].z, f[2].w);
    uint32_t l6 = pack_lo(f[3].x, f[3].y), l7 = pack_lo(f[3].z, f[3].w);
    STS128(l4, l5, l6, l7, lo_addr + 16);
}

__device__ __forceinline__ void ldg16(float4* pf, const float* src, bool valid)
{
    if (valid) {
        const float4* p = (const float4*)src;
        pf[0] = p[0]; pf[1] = p[1]; pf[2] = p[2]; pf[3] = p[3];
    } else {
        pf[0] = pf[1] = pf[2] = pf[3] = make_float4(0.f, 0.f, 0.f, 0.f);
    }
}

// ---------------- gate + noaux_tc routing (8 tokens / block) ----------------
__global__ __launch_bounds__(256) void gate_kernel(const float* __restrict__ x,
                                                   const float* __restrict__ gate_w,
                                                   const float* __restrict__ e_bias)
{
    __shared__ float xs[8][H / 8 * 8];   // 8 x 1024
    __shared__ float s_sc[8][E];
    __shared__ float s_sfc[8][E];

    int tid = threadIdx.x;
    int wid = tid >> 5;
    int lane = tid & 31;
    int tok0 = blockIdx.x * 8;

    float4* xs4 = (float4*)&xs[0][0];
    const float4* xr = (const float4*)(x + (size_t)tok0 * H);
    for (int i = tid; i < 8 * H / 4; i += 256) xs4[i] = xr[i];
    __syncthreads();

    {
        const float4* w4 = (const float4*)(gate_w + (size_t)lane * H);
        const float4* xv = (const float4*)&xs[wid][0];
        float acc = 0.f;
#pragma unroll 8
        for (int i = 0; i < H / 4; i++) {
            float4 a = xv[i]; float4 b = w4[i];
            acc += a.x * b.x; acc += a.y * b.y; acc += a.z * b.z; acc += a.w * b.w;
        }
        float sc = 1.f / (1.f + expf(-acc));
        s_sc[wid][lane] = sc;
        s_sfc[wid][lane] = sc + e_bias[lane];
    }
    __syncwarp();

    if (lane == 0) {
        int t = tok0 + wid;
        float* sfc = s_sfc[wid];
        float* scores = s_sc[wid];
        float gs[G];
#pragma unroll
        for (int g = 0; g < G; g++) {
            float a0 = sfc[4*g], a1 = sfc[4*g+1], a2 = sfc[4*g+2], a3 = sfc[4*g+3];
            float h1 = fmaxf(a0, a1), l1 = fminf(a0, a1);
            float h2 = fmaxf(a2, a3), l2 = fminf(a2, a3);
            gs[g] = fmaxf(h1, h2) + fmaxf(fminf(h1, h2), fmaxf(l1, l2));
        }
        bool sel[G];
#pragma unroll
        for (int g = 0; g < G; g++) sel[g] = false;
        for (int r = 0; r < TG; r++) {
            int best = -1; float bv = -1e30f;
            for (int g = 0; g < G; g++)
                if (!sel[g] && gs[g] > bv) { bv = gs[g]; best = g; }
            sel[best] = true;
        }
        float m[E];
        for (int e2 = 0; e2 < E; e2++) m[e2] = sel[e2 >> 2] ? sfc[e2] : 0.f;
        int idx[KTOP]; float w[KTOP]; float s = 0.f;
        for (int r = 0; r < KTOP; r++) {
            int best = 0; float bv = -1e30f;
            for (int e2 = 0; e2 < E; e2++)
                if (m[e2] > bv) { bv = m[e2]; best = e2; }
            m[best] = -1e30f;
            idx[r] = best; w[r] = scores[best]; s += w[r];
        }
        s += 1e-20f;
        for (int r = 0; r < KTOP; r++) {
            g_topk_idx[t * KTOP + r] = idx[r];
            g_tw[t * KTOP + r] = w[r] / s * SCALEF;
        }
    }
}

// ---------------- parallel capacity dispatch (segmented scan) ----------------
__global__ __launch_bounds__(1024) void dispatch_kernel()
{
    __shared__ int ef[T * KTOP];        // 16 KB
    __shared__ int posseg[T * KTOP];    // 16 KB
    __shared__ int scnt[32][E];         // 4 KB

    int tid = threadIdx.x;
    int wid = tid >> 5;
    int lane = tid & 31;

    for (int i = tid; i < T * KTOP; i += 1024) ef[i] = g_topk_idx[i];
    ((int*)scnt)[tid] = 0;
    __syncthreads();

    // step 1: per-warp segment of 128 elements, sequential 4 rounds of 32
#pragma unroll
    for (int r = 0; r < 4; r++) {
        int j = wid * 128 + r * 32 + lane;
        int e = ef[j];
        unsigned mask = __match_any_sync(0xffffffffu, e);
        int prior = __popc(mask & ((1u << lane) - 1u));
        int base = scnt[wid][e];
        __syncwarp();
        if (lane == (__ffs(mask) - 1)) scnt[wid][e] = base + __popc(mask);
        __syncwarp();
        posseg[j] = base + prior;
    }
    __syncthreads();

    // step 2: exclusive prefix across the 32 segments, per expert (lane=expert)
    if (wid == 0) {
        int run = 0;
#pragma unroll
        for (int w = 0; w < 32; w++) {
            int c = scnt[w][lane];
            scnt[w][lane] = run;
            run += c;
        }
        g_expert_count[lane] = run < CAP ? run : CAP;
    }
    __syncthreads();

    // step 3: final positions + slot tables
    for (int i = tid; i < T * KTOP; i += 1024) {
        int e = ef[i];
        int pos = scnt[i >> 7][e] + posseg[i];
        if (pos < CAP) {
            g_slot_token[e * CAP + pos] = i >> 2;
            g_token_slot[i] = e * CAP + pos;
        } else {
            g_token_slot[i] = -1;
        }
    }
}

// ---------------- unified bf16-split mma.sync GEMM (double-buffered) ----------------
// C[M,N] = A[M,K] . B[N,K]^T   block 128x128, warp 64x32, K-chunk 32
// PHASE 1: expert gate_up (blocks [0,512)) + shared gate_up (blocks [512,640))
// PHASE 2: expert down    (blocks [0,512)) + shared down    (blocks [512,576))
#define ROWB 80            // smem row pitch bytes (64B data + 16B pad)
#define PLANE (128 * ROWB) // 10240 bytes per plane
#define STAGE (4 * PLANE)  // Ah | Al | Bh | Bl = 40960 bytes

template<int PHASE>
__global__ __launch_bounds__(256, 2) void mma_gemm(
    const float* __restrict__ x,
    const float* __restrict__ wgu,  const float* __restrict__ wdn,
    const float* __restrict__ wgus, const float* __restrict__ wds,
    float* __restrict__ out)
{
    extern __shared__ char dynsmem[];
    __shared__ int s_toks[128];

    const int bid = blockIdx.x;
    const bool expert = bid < 512;

    int e = 0, n0, row0;
    if (expert) {
        e = bid >> 4;
        int rem = bid & 15;
        n0 = (rem & 7) * 128;
        row0 = (rem >> 3) * 128;
        if (row0 >= g_expert_count[e]) return;
    } else {
        int b = bid - 512;
        if (PHASE == 1) { n0 = (b & 15) * 128; row0 = (b >> 4) * 128; }
        else            { n0 = (b & 7)  * 128; row0 = (b >> 3) * 128; }
    }

    const int tid = threadIdx.x;
    const int wid = tid >> 5;
    const int lane = tid & 31;

    if (PHASE == 1 && expert) {
        if (tid < 128) {
            int r = row0 + tid;
            s_toks[tid] = (r < g_expert_count[e]) ? g_slot_token[e * CAP + r] : -1;
        }
        __syncthreads();
    }

    // ---- loader mapping: thread -> row r = tid/2, 16-float half c0 ----
    const int r  = tid >> 1;
    const int c0 = (tid & 1) * 16;

    const float* aptr;
    const float* bptr;
    bool avalid = true;
    int KD;
    if (PHASE == 1) {
        KD = 1024;
        if (expert) {
            int tok = s_toks[r];
            avalid = (tok >= 0);
            aptr = x + (size_t)(avalid ? tok : 0) * H + c0;
            bptr = wgu + ((size_t)e * 2 * II + n0 + r) * H + c0;
        } else {
            aptr = x + (size_t)(row0 + r) * H + c0;
            bptr = wgus + (size_t)(n0 + r) * H + c0;
        }
    } else {
        if (expert) {
            KD = II;
            aptr = g_act + ((size_t)e * CAP + row0 + r) * II + c0;
            bptr = wdn + ((size_t)e * H + n0 + r) * II + c0;
        } else {
            KD = 1024;
            aptr = g_shared_act + (size_t)(row0 + r) * IS + c0;
            bptr = wds + (size_t)(n0 + r) * IS + c0;
        }
    }
    const int NCH = KD / 32;

    const uint32_t sdyn = smem_u32(dynsmem);
    const uint32_t sa_off = (uint32_t)(r * ROWB + c0 * 2);            // within Ah plane
    const uint32_t sb_off = (uint32_t)(2 * PLANE + r * ROWB + c0 * 2);// within stage (Bh)

    // ---- compute mapping ----
    const int warp_m = wid >> 2;
    const int warp_n = wid & 3;
    const uint32_t a_off = (uint32_t)((warp_m * 64 + (lane & 15)) * ROWB + ((lane >> 4) << 4));
    const uint32_t b_off = (uint32_t)(2 * PLANE + (warp_n * 32 + (lane & 7)) * ROWB + (((lane >> 3) & 1) << 4));

    float acc[4][4][4];
#pragma unroll
    for (int mt = 0; mt < 4; mt++)
#pragma unroll
        for (int nt = 0; nt < 4; nt++)
#pragma unroll
            for (int q = 0; q < 4; q++) acc[mt][nt][q] = 0.f;

#define COMPUTE_S(base, s) do { \
    uint32_t bh[4][2], bl[4][2]; \
    _Pragma("unroll") \
    for (int nt = 0; nt < 4; nt++) { \
        uint32_t addr = (base) + b_off + (uint32_t)(nt * 8 * ROWB + (s) * 32); \
        LDSM_X2(bh[nt][0], bh[nt][1], addr); \
        LDSM_X2(bl[nt][0], bl[nt][1], addr + PLANE); \
    } \
    _Pragma("unroll") \
    for (int mt = 0; mt < 4; mt++) { \
        uint32_t addr = (base) + a_off + (uint32_t)(mt * 16 * ROWB + (s) * 32); \
        uint32_t ah0, ah1, ah2, ah3, al0, al1, al2, al3; \
        LDSM_X4(ah0, ah1, ah2, ah3, addr); \
        LDSM_X4(al0, al1, al2, al3, addr + PLANE); \
        _Pragma("unroll") \
        for (int nt = 0; nt < 4; nt++) { \
            MMA16816(acc[mt][nt], ah0, ah1, ah2, ah3, bh[nt][0], bh[nt][1]); \
            MMA16816(acc[mt][nt], ah0, ah1, ah2, ah3, bl[nt][0], bl[nt][1]); \
            MMA16816(acc[mt][nt], al0, al1, al2, al3, bh[nt][0], bh[nt][1]); \
        } \
    } \
} while (0)

    // ---- prologue: stage chunk 0 into buffer 0 ----
    {
        float4 pf[4];
        ldg16(pf, aptr, avalid);
        sts_chunk16(sdyn + sa_off, sdyn + PLANE + sa_off, pf);
        ldg16(pf, bptr, true);
        sts_chunk16(sdyn + sb_off, sdyn + PLANE + sb_off, pf);
    }
    __syncthreads();

    // ---- main loop: one barrier per chunk, loads overlapped with MMA ----
    for (int kc = 0; kc < NCH; kc++) {
        const uint32_t cur = sdyn + (uint32_t)(kc & 1) * STAGE;
        const uint32_t nxt = sdyn + (uint32_t)((kc + 1) & 1) * STAGE;
        const bool hn = (kc + 1 < NCH);

        float4 pf[4];
        if (hn) ldg16(pf, aptr + (kc + 1) * 32, avalid);
        COMPUTE_S(cur, 0);
        if (hn) {
            sts_chunk16(nxt + sa_off, nxt + PLANE + sa_off, pf);
            ldg16(pf, bptr + (kc + 1) * 32, true);
        }
        COMPUTE_S(cur, 1);
        if (hn) sts_chunk16(nxt + sb_off, nxt + PLANE + sb_off, pf);
        __syncthreads();
    }
#undef COMPUTE_S

    // ---- epilogue: plain fp32 stores ----
    float* Cb;
    int CSTR;
    if (PHASE == 1) {
        if (expert) { Cb = g_gu + (size_t)e * CAP * 2 * II; CSTR = 2 * II; }
        else        { Cb = g_shared_gu;                     CSTR = 2 * IS; }
    } else {
        if (expert) { Cb = g_ye + (size_t)e * CAP * H;      CSTR = H; }
        else        { Cb = out;                             CSTR = H; }
    }

#pragma unroll
    for (int mt = 0; mt < 4; mt++) {
        int row = row0 + warp_m * 64 + mt * 16 + (lane >> 2);
#pragma unroll
        for (int nt = 0; nt < 4; nt++) {
            int col = n0 + warp_n * 32 + nt * 8 + (lane & 3) * 2;
            *(float2*)(Cb + (size_t)row * CSTR + col) =
                make_float2(acc[mt][nt][0], acc[mt][nt][1]);
            *(float2*)(Cb + (size_t)(row + 8) * CSTR + col) =
                make_float2(acc[mt][nt][2], acc[mt][nt][3]);
        }
    }
}

// ---------------- merged silu-and-mul ----------------
__device__ __forceinline__ float4 silu_mul4(float4 g, float4 u) {
    float4 r;
    r.x = g.x / (1.f + expf(-g.x)) * u.x;
    r.y = g.y / (1.f + expf(-g.y)) * u.y;
    r.z = g.z / (1.f + expf(-g.z)) * u.z;
    r.w = g.w / (1.f + expf(-g.w)) * u.w;
    return r;
}

#define SHN (T * IS / 4)            // 262144 float4 units (shared)
#define EXN (E * CAP * II / 4)      // 1048576 float4 units (expert)

__global__ void silu_kernel()
{
    int idx = blockIdx.x * 256 + threadIdx.x;
    if (idx < SHN) {
        int r = idx / (IS / 4), i = idx % (IS / 4);
        float4 g = *(const float4*)&g_shared_gu[(size_t)r * 2 * IS + i * 4];
        float4 u = *(const float4*)&g_shared_gu[(size_t)r * 2 * IS + IS + i * 4];
        *(float4*)&g_shared_act[(size_t)r * IS + i * 4] = silu_mul4(g, u);
    } else {
        int j = idx - SHN;
        int r = j / (II / 4), i = j % (II / 4);
        float4 g = *(const float4*)&g_gu[(size_t)r * 2 * II + i * 4];
        float4 u = *(const float4*)&g_gu[(size_t)r * 2 * II + II + i * 4];
        *(float4*)&g_act[(size_t)r * II + i * 4] = silu_mul4(g, u);
    }
}

// ---------------- final combine: out += sum_k w_k * ye[slot] ----------------
__global__ void combine_kernel(float* __restrict__ out)
{
    int t = blockIdx.x;
    int h4 = threadIdx.x;
    float4* orow = (float4*)(out + (size_t)t * H);
    float4 acc = orow[h4];
#pragma unroll
    for (int k = 0; k < KTOP; k++) {
        int slot = g_token_slot[t * KTOP + k];
        if (slot >= 0) {
            float w = g_tw[t * KTOP + k];
            float4 y = ((const float4*)(g_ye + (size_t)slot * H))[h4];
            acc.x += w * y.x; acc.y += w * y.y; acc.z += w * y.z; acc.w += w * y.w;
        }
    }
    orow[h4] = acc;
}

// ---------------- launcher ----------------
extern "C" void kernel_launch(void* const* d_in, const int* in_sizes, int n_in,
                              void* d_out, int out_size)
{
    (void)in_sizes; (void)n_in; (void)out_size;
    const float* x    = (const float*)d_in[0];   // (T,H)
    const float* gw   = (const float*)d_in[1];   // (E,H)
    const float* eb   = (const float*)d_in[2];   // (E,)
    const float* wgu  = (const float*)d_in[3];   // (E,2I,H)
    const float* wdn  = (const float*)d_in[4];   // (E,H,I)
    const float* wgus = (const float*)d_in[5];   // (2*IS,H)
    const float* wds  = (const float*)d_in[6];   // (H,IS)
    float* out = (float*)d_out;                  // (T,H)

    constexpr int DSMEM = 2 * STAGE;  // 81920
    static bool attr_done = false;
    if (!attr_done) {
        cudaFuncSetAttribute((const void*)mma_gemm<1>,
                             cudaFuncAttributeMaxDynamicSharedMemorySize, DSMEM);
        cudaFuncSetAttribute((const void*)mma_gemm<2>,
                             cudaFuncAttributeMaxDynamicSharedMemorySize, DSMEM);
        attr_done = true;
    }

    gate_kernel<<<T / 8, 256>>>(x, gw, eb);
    dispatch_kernel<<<1, 1024>>>();

    // gate_up GEMMs: expert (512 blocks) + shared (128 blocks)
    mma_gemm<1><<<640, 256, DSMEM>>>(x, wgu, wdn, wgus, wds, out);
    silu_kernel<<<(SHN + EXN) / 256, 256>>>();
    // down GEMMs: expert (512 blocks) + shared (64 blocks)
    mma_gemm<2><<<576, 256, DSMEM>>>(x, wgu, wdn, wgus, wds, out);

    combine_kernel<<<T, 256>>>(out);
}